// round 17
// baseline (speedup 1.0000x reference)
#include <cuda_runtime.h>
#include <cuda_fp16.h>
#include <math.h>
#include <stdint.h>

#define N_NODES 50000
#define N_EDGES 800000
#define IN_F 256
#define OUT_F 32
#define NHEAD 8
#define EDGE_F 32
#define N_ETYPES 8
#define NEG_SLOPE 0.1f

#define HD (NHEAD * OUT_F)            // 256
#define OUT_ELEMS (N_NODES * HD)
#define ATT_ELEMS (N_EDGES * NHEAD)
#define SCAN_NB ((N_NODES + 1023) / 1024)
#define PACK_MASK 0xFFFFF

// ---------------- scratch ----------------
__device__ __half    g_h16[N_NODES * HD];
__device__ float     g_hl[N_NODES * NHEAD];
__device__ float     g_hr[N_NODES * NHEAD];
__device__ float     g_he[N_ETYPES * NHEAD];
__device__ int       g_deg[N_NODES];           // zero-init at load; re-zeroed by aggregate
__device__ int       g_off[N_NODES];
__device__ int       g_wptr[N_NODES];
__device__ int       g_bsum[SCAN_NB];
__device__ int       g_spack[N_EDGES];         // sorted pos -> row | (tp<<20)
__device__ int       g_eidx[N_EDGES];          // sorted pos -> edge id
__device__ __half    g_wh[HD * IN_F];          // [n][k] = fp16(W[k][n])

// ---------------- K_wprep (+ he) ----------------
__global__ void k_wprep(const float* __restrict__ W,
                        const float* __restrict__ edge_emb,
                        const float* __restrict__ W_e,
                        const float* __restrict__ a_e) {
    int idx = blockIdx.x * blockDim.x + threadIdx.x;
    if (blockIdx.x == 0 && threadIdx.x < N_ETYPES * NHEAD) {
        int t = threadIdx.x >> 3, h = threadIdx.x & 7;
        float acc = 0.0f;
        for (int f = 0; f < EDGE_F; f++) {
            float ev = 0.0f;
            for (int k = 0; k < EDGE_F; k++)
                ev += edge_emb[t * EDGE_F + k] * W_e[k * (EDGE_F * NHEAD) + h * EDGE_F + f];
            acc += a_e[h * EDGE_F + f] * ev;
        }
        g_he[t * NHEAD + h] = acc;
    }
    if (idx >= HD * IN_F) return;
    int n = idx >> 8, k = idx & 255;
    g_wh[n * IN_F + k] = __float2half_rn(W[k * HD + n]);
}

// ---------------- K2: pipelined single-pass fp16 mma.sync GEMM ------------------
#define XPAD 40
#define WPAD 40
#define OFF_XH 0
#define OFF_WB (OFF_XH + 128 * XPAD)      // 5120: W double buffers start
#define WBUF_HALVES (256 * WPAD)          // 10240 per buffer
#define SM_HALVES (OFF_WB + 2 * WBUF_HALVES)  // 25600 halves = 51200 B

__device__ __forceinline__ void mma_fp16(float* d, uint32_t a0, uint32_t a1,
                                         uint32_t a2, uint32_t a3,
                                         uint32_t b0, uint32_t b1) {
    asm volatile(
        "mma.sync.aligned.m16n8k16.row.col.f32.f16.f16.f32 "
        "{%0,%1,%2,%3}, {%4,%5,%6,%7}, {%8,%9}, {%0,%1,%2,%3};"
        : "+f"(d[0]), "+f"(d[1]), "+f"(d[2]), "+f"(d[3])
        : "r"(a0), "r"(a1), "r"(a2), "r"(a3), "r"(b0), "r"(b1));
}
__device__ __forceinline__ float nanfix(float v) { return isnan(v) ? 0.0f : v; }
__device__ __forceinline__ uint32_t smem_u32(const void* p) {
    uint32_t a;
    asm("{ .reg .u64 t; cvta.to.shared.u64 t, %1; cvt.u32.u64 %0, t; }" : "=r"(a) : "l"(p));
    return a;
}
#define CP_ASYNC16(dst_u32, src_ptr) \
    asm volatile("cp.async.ca.shared.global [%0], [%1], 16;" :: "r"(dst_u32), "l"(src_ptr))
#define CP_COMMIT() asm volatile("cp.async.commit_group;")
#define CP_WAIT0()  asm volatile("cp.async.wait_group 0;")

__global__ __launch_bounds__(512) void k_gemm_mma(const float* __restrict__ x,
                                                  const float* __restrict__ a_l,
                                                  const float* __restrict__ a_r) {
    extern __shared__ __align__(16) uint16_t sm[];
    uint16_t* sXh = sm + OFF_XH;
    uint32_t sb = smem_u32(sm);

    int tid = threadIdx.x;
    int lane = tid & 31;
    int wid = tid >> 5;          // 0..15
    int warp_m = wid & 7;
    int warp_n = wid >> 3;
    int m0 = blockIdx.x * 128;

    float acc[16][4];
#pragma unroll
    for (int t = 0; t < 16; t++)
#pragma unroll
        for (int j = 0; j < 4; j++) acc[t][j] = 0.0f;

    int wn = tid >> 1;
    int wj0 = (tid & 1) * 2;
    int xr = tid >> 2, xq = tid & 3;
    int gm = m0 + xr;
    const float4* xsrc = (gm < N_NODES)
        ? reinterpret_cast<const float4*>(x + gm * IN_F + xq * 8) : nullptr;

    float v[8];
    {
        uint32_t dWh = sb + (OFF_WB + wn * WPAD) * 2;
        const __half* srch = g_wh + wn * IN_F;
#pragma unroll
        for (int j = 0; j < 2; j++)
            CP_ASYNC16(dWh + (wj0 + j) * 16, srch + (wj0 + j) * 8);
        CP_COMMIT();
        if (xsrc) {
            float4 f0 = xsrc[0], f1 = xsrc[1];
            v[0] = f0.x; v[1] = f0.y; v[2] = f0.z; v[3] = f0.w;
            v[4] = f1.x; v[5] = f1.y; v[6] = f1.z; v[7] = f1.w;
        } else {
#pragma unroll
            for (int j = 0; j < 8; j++) v[j] = 0.0f;
        }
        uint32_t hi[4];
#pragma unroll
        for (int j = 0; j < 4; j++) {
            __half2 p = __floats2half2_rn(v[2 * j], v[2 * j + 1]);
            hi[j] = *reinterpret_cast<uint32_t*>(&p);
        }
        *reinterpret_cast<uint4*>(&sXh[xr * XPAD + xq * 8]) = make_uint4(hi[0], hi[1], hi[2], hi[3]);
        CP_WAIT0();
        __syncthreads();
    }

    for (int ks = 0; ks < 8; ks++) {
        int buf = ks & 1;
        if (ks < 7) {
            int k1 = (ks + 1) * 32;
            uint32_t dWh = sb + (OFF_WB + (1 - buf) * WBUF_HALVES + wn * WPAD) * 2;
            const __half* srch = g_wh + wn * IN_F + k1;
#pragma unroll
            for (int j = 0; j < 2; j++)
                CP_ASYNC16(dWh + (wj0 + j) * 16, srch + (wj0 + j) * 8);
            CP_COMMIT();
            if (xsrc) {
                float4 f0 = xsrc[(ks + 1) * 8];
                float4 f1 = xsrc[(ks + 1) * 8 + 1];
                v[0] = f0.x; v[1] = f0.y; v[2] = f0.z; v[3] = f0.w;
                v[4] = f1.x; v[5] = f1.y; v[6] = f1.z; v[7] = f1.w;
            }
        }
        const uint16_t* sWh = sm + OFF_WB + buf * WBUF_HALVES;
#pragma unroll
        for (int kin = 0; kin < 32; kin += 16) {
            int c = (lane & 3) * 2 + kin;
            int ra = (warp_m * 16 + (lane >> 2)) * XPAD;
            uint32_t ah0 = *reinterpret_cast<const uint32_t*>(&sXh[ra + c]);
            uint32_t ah1 = *reinterpret_cast<const uint32_t*>(&sXh[ra + 8 * XPAD + c]);
            uint32_t ah2 = *reinterpret_cast<const uint32_t*>(&sXh[ra + c + 8]);
            uint32_t ah3 = *reinterpret_cast<const uint32_t*>(&sXh[ra + 8 * XPAD + c + 8]);
#pragma unroll
            for (int t = 0; t < 16; t++) {
                int nb = (warp_n * 128 + t * 8 + (lane >> 2)) * WPAD + (lane & 3) * 2 + kin;
                uint32_t bh0 = *reinterpret_cast<const uint32_t*>(&sWh[nb]);
                uint32_t bh1 = *reinterpret_cast<const uint32_t*>(&sWh[nb + 8]);
                mma_fp16(acc[t], ah0, ah1, ah2, ah3, bh0, bh1);
            }
        }
        if (ks < 7) {
            __syncthreads();
            uint32_t hi[4];
#pragma unroll
            for (int j = 0; j < 4; j++) {
                __half2 p = __floats2half2_rn(v[2 * j], v[2 * j + 1]);
                hi[j] = *reinterpret_cast<uint32_t*>(&p);
            }
            *reinterpret_cast<uint4*>(&sXh[xr * XPAD + xq * 8]) = make_uint4(hi[0], hi[1], hi[2], hi[3]);
            CP_WAIT0();
            __syncthreads();
        }
    }

    int r = lane >> 2;
    int gr0 = m0 + warp_m * 16 + r;
    int gr1 = gr0 + 8;
    bool ok0 = (gr0 < N_NODES), ok1 = (gr1 < N_NODES);
    float dl0[4] = {0, 0, 0, 0}, dl1[4] = {0, 0, 0, 0};
    float dr0[4] = {0, 0, 0, 0}, dr1[4] = {0, 0, 0, 0};
#pragma unroll
    for (int t = 0; t < 16; t++) {
        int n = warp_n * 128 + t * 8 + (lane & 3) * 2;
        float v0 = nanfix(acc[t][0]), v1 = nanfix(acc[t][1]);
        float v2 = nanfix(acc[t][2]), v3 = nanfix(acc[t][3]);
        float alv0 = __ldg(&a_l[n]), alv1 = __ldg(&a_l[n + 1]);
        float arv0 = __ldg(&a_r[n]), arv1 = __ldg(&a_r[n + 1]);
        int hh = t >> 2;
        dl0[hh] += v0 * alv0 + v1 * alv1;
        dr0[hh] += v0 * arv0 + v1 * arv1;
        dl1[hh] += v2 * alv0 + v3 * alv1;
        dr1[hh] += v2 * arv0 + v3 * arv1;
        if (ok0) *reinterpret_cast<__half2*>(&g_h16[gr0 * HD + n]) = __floats2half2_rn(v0, v1);
        if (ok1) *reinterpret_cast<__half2*>(&g_h16[gr1 * HD + n]) = __floats2half2_rn(v2, v3);
    }
#pragma unroll
    for (int hh = 0; hh < 4; hh++) {
#pragma unroll
        for (int o = 1; o <= 2; o <<= 1) {
            dl0[hh] += __shfl_xor_sync(0xffffffffu, dl0[hh], o);
            dl1[hh] += __shfl_xor_sync(0xffffffffu, dl1[hh], o);
            dr0[hh] += __shfl_xor_sync(0xffffffffu, dr0[hh], o);
            dr1[hh] += __shfl_xor_sync(0xffffffffu, dr1[hh], o);
        }
    }
    if ((lane & 3) == 0) {
#pragma unroll
        for (int hh = 0; hh < 4; hh++) {
            int head = warp_n * 4 + hh;
            if (ok0) { g_hl[gr0 * NHEAD + head] = dl0[hh]; g_hr[gr0 * NHEAD + head] = dr0[hh]; }
            if (ok1) { g_hl[gr1 * NHEAD + head] = dl1[hh]; g_hr[gr1 * NHEAD + head] = dr1[hh]; }
        }
    }
}

// ---------------- CSR build ----------------
__global__ void k_hist(const int* __restrict__ col) {
    int e = blockIdx.x * blockDim.x + threadIdx.x;
    if (e < N_EDGES) atomicAdd(&g_deg[__ldg(&col[e])], 1);
}
__global__ __launch_bounds__(1024) void k_scan1() {
    __shared__ int sh[1024];
    int t = threadIdx.x;
    int idx = blockIdx.x * 1024 + t;
    int v = (idx < N_NODES) ? g_deg[idx] : 0;
    sh[t] = v;
    __syncthreads();
#pragma unroll
    for (int off = 1; off < 1024; off <<= 1) {
        int add = (t >= off) ? sh[t - off] : 0;
        __syncthreads();
        sh[t] += add;
        __syncthreads();
    }
    if (idx < N_NODES) g_off[idx] = sh[t] - v;
    if (t == 1023) g_bsum[blockIdx.x] = sh[t];
}
__global__ __launch_bounds__(1024) void k_scan23() {
    __shared__ int s_base;
    int t = threadIdx.x;
    int bid = blockIdx.x;
    if (t < 32) {
        int v = 0;
        for (int j = t; j < SCAN_NB; j += 32)
            if (j < bid) v += g_bsum[j];
#pragma unroll
        for (int o = 16; o; o >>= 1) v += __shfl_xor_sync(0xffffffffu, v, o);
        if (t == 0) s_base = v;
    }
    __syncthreads();
    int idx = bid * 1024 + t;
    if (idx < N_NODES) {
        int o = g_off[idx] + s_base;
        g_off[idx] = o;
        g_wptr[idx] = o;
    }
}
__global__ void k_scatter(const int* __restrict__ col, const int* __restrict__ row,
                          const int* __restrict__ tp) {
    int e = blockIdx.x * blockDim.x + threadIdx.x;
    if (e >= N_EDGES) return;
    int c = __ldg(&col[e]);
    int pos = atomicAdd(&g_wptr[c], 1);
    g_spack[pos] = __ldg(&row[e]) | (__ldg(&tp[e]) << 20);
    g_eidx[pos] = e;
}

// ---------------- K5: fused edge-softmax + gather + normalize + attOut ----------
__device__ __forceinline__ float edge_ex(float hlv, float hrv, float hev) {
    float s = hlv + hrv + hev;
    s = (s > 0.0f) ? s : NEG_SLOPE * s;
    return __expf(s);
}

__global__ __launch_bounds__(256) void k_aggregate(float* __restrict__ out,
                                                   float* __restrict__ attOut) {
    int tid = threadIdx.x;
    int lane = tid & 31;
    int n = blockIdx.x * 8 + (tid >> 5);
    if (n >= N_NODES) return;
    int head = lane >> 2;

    int base = g_off[n];
    int deg = g_deg[n];
    const uint4* h4 = reinterpret_cast<const uint4*>(g_h16);
    float hrv = g_hr[n * NHEAD + head];

    float acc[8];
#pragma unroll
    for (int j = 0; j < 8; j++) acc[j] = 0.0f;
    float zacc = 0.f;

    int k = 0;
    for (; k + 4 <= deg; k += 4) {
        int v[4];
#pragma unroll
        for (int j = 0; j < 4; j++) v[j] = __ldg(&g_spack[base + k + j]);
        int r[4];
#pragma unroll
        for (int j = 0; j < 4; j++) r[j] = v[j] & PACK_MASK;
        uint4 u[4];
#pragma unroll
        for (int j = 0; j < 4; j++) u[j] = h4[r[j] * 32 + lane];
        float hl[4];
#pragma unroll
        for (int j = 0; j < 4; j++) hl[j] = __ldg(&g_hl[r[j] * NHEAD + head]);
        float ex[4];
#pragma unroll
        for (int j = 0; j < 4; j++)
            ex[j] = edge_ex(hl[j], hrv, g_he[(v[j] >> 20) * NHEAD + head]);
#pragma unroll
        for (int j = 0; j < 4; j++) {
            float2 p0 = __half22float2(*reinterpret_cast<__half2*>(&u[j].x));
            float2 p1 = __half22float2(*reinterpret_cast<__half2*>(&u[j].y));
            float2 p2 = __half22float2(*reinterpret_cast<__half2*>(&u[j].z));
            float2 p3 = __half22float2(*reinterpret_cast<__half2*>(&u[j].w));
            acc[0] += ex[j] * p0.x; acc[1] += ex[j] * p0.y;
            acc[2] += ex[j] * p1.x; acc[3] += ex[j] * p1.y;
            acc[4] += ex[j] * p2.x; acc[5] += ex[j] * p2.y;
            acc[6] += ex[j] * p3.x; acc[7] += ex[j] * p3.y;
            zacc += ex[j];
        }
    }
    for (; k < deg; k++) {
        int v0 = __ldg(&g_spack[base + k]);
        int r0 = v0 & PACK_MASK;
        float ex0 = edge_ex(__ldg(&g_hl[r0 * NHEAD + head]), hrv,
                            g_he[(v0 >> 20) * NHEAD + head]);
        uint4 u0 = h4[r0 * 32 + lane];
        float2 p0 = __half22float2(*reinterpret_cast<__half2*>(&u0.x));
        float2 p1 = __half22float2(*reinterpret_cast<__half2*>(&u0.y));
        float2 p2 = __half22float2(*reinterpret_cast<__half2*>(&u0.z));
        float2 p3 = __half22float2(*reinterpret_cast<__half2*>(&u0.w));
        acc[0] += ex0 * p0.x; acc[1] += ex0 * p0.y;
        acc[2] += ex0 * p1.x; acc[3] += ex0 * p1.y;
        acc[4] += ex0 * p2.x; acc[5] += ex0 * p2.y;
        acc[6] += ex0 * p3.x; acc[7] += ex0 * p3.y;
        zacc += ex0;
    }
    float inv = (deg > 0) ? (1.0f / zacc) : 0.0f;
    float4* o4 = reinterpret_cast<float4*>(out) + n * 64 + lane * 2;
    o4[0] = make_float4(acc[0] * inv, acc[1] * inv, acc[2] * inv, acc[3] * inv);
    o4[1] = make_float4(acc[4] * inv, acc[5] * inv, acc[6] * inv, acc[7] * inv);

    // re-zero deg for the next graph replay (invariant: deg==0 before k_hist)
    if (lane == 0) g_deg[n] = 0;

    // ---- fused attOut: second pass, lanes 0-7 handle the 8 heads ----
    if (attOut) {
        int myhead = lane & 7;
        float invh = __shfl_sync(0xffffffffu, inv, myhead * 4);
        float hrv8 = g_hr[n * NHEAD + myhead];
        for (int kk = 0; kk < deg; kk++) {
            int v0 = __ldg(&g_spack[base + kk]);    // warp-uniform broadcast
            int e0 = __ldg(&g_eidx[base + kk]);
            if (lane < 8) {
                int r0 = v0 & PACK_MASK;
                float ex = edge_ex(__ldg(&g_hl[r0 * NHEAD + myhead]), hrv8,
                                   g_he[(v0 >> 20) * NHEAD + myhead]);
                attOut[e0 * NHEAD + myhead] = ex * invh;
            }
        }
    }
}

// ---------------- launch ---------------------------------------------------------
extern "C" void kernel_launch(void* const* d_in, const int* in_sizes, int n_in,
                              void* d_out, int out_size) {
    const float* x        = (const float*)d_in[0];
    const float* W        = (const float*)d_in[1];
    const float* W_e      = (const float*)d_in[2];
    const float* edge_emb = (const float*)d_in[3];
    const float* a_l      = (const float*)d_in[4];
    const float* a_r      = (const float*)d_in[5];
    const float* a_e      = (const float*)d_in[6];
    const int*   row      = (const int*)d_in[7];
    const int*   col      = (const int*)d_in[8];
    const int*   tp       = (const int*)d_in[9];

    float* out = (float*)d_out;
    float* attOut = (out_size >= OUT_ELEMS + ATT_ELEMS) ? out + OUT_ELEMS : nullptr;

    static cudaStream_t s1 = nullptr;
    static cudaEvent_t evFork = nullptr, evCsr = nullptr;
    static int inited = 0;
    if (!inited) {
        cudaFuncSetAttribute(k_gemm_mma, cudaFuncAttributeMaxDynamicSharedMemorySize,
                             SM_HALVES * 2);
        cudaStreamCreateWithFlags(&s1, cudaStreamNonBlocking);
        cudaEventCreateWithFlags(&evFork, cudaEventDisableTiming);
        cudaEventCreateWithFlags(&evCsr, cudaEventDisableTiming);
        inited = 1;
    }

    cudaEventRecord(evFork, 0);
    cudaStreamWaitEvent(s1, evFork, 0);

    k_hist<<<(N_EDGES + 255) / 256, 256, 0, s1>>>(col);
    k_scan1<<<SCAN_NB, 1024, 0, s1>>>();
    k_scan23<<<SCAN_NB, 1024, 0, s1>>>();
    k_scatter<<<(N_EDGES + 255) / 256, 256, 0, s1>>>(col, row, tp);
    cudaEventRecord(evCsr, s1);

    k_wprep<<<(HD * IN_F + 255) / 256, 256>>>(W, edge_emb, W_e, a_e);
    k_gemm_mma<<<(N_NODES + 127) / 128, 512, SM_HALVES * 2>>>(x, a_l, a_r);

    cudaStreamWaitEvent(0, evCsr, 0);
    k_aggregate<<<(N_NODES + 7) / 8, 256>>>(out, attOut);
}